// round 8
// baseline (speedup 1.0000x reference)
#include <cuda_runtime.h>
#include <cuda_bf16.h>

// social_stgcn_46462956208716
//
// The reference ends with log_softmax over a length-1 axis:
//     out = gcn_conv(h, edge_index, W2, b2)   # [16384, 1]
//     return jax.nn.log_softmax(out, axis=1)  # x - logsumexp([x]) == 0
// For any finite input this is identically zero; all inputs are finite.
// Output = zeros([16384, 1]) exactly.
//
// Session measurements (all functionally identical zero-writers):
//   R1 16x256 + tail : 4.86 | R2 4x1024 : 4.61 | R3 memset : 4.83
//   R4 32x128        : 5.63 | R5 4x1024 : 4.61 (exact repro of R2)
//   R6 1x1024        : infra failure (container), resubmitting unchanged.
// Launch/replay-bound; this probes the last geometry point: a single CTA
// (no multi-CTA rasterization). 1024 threads x 4 float4 stores each covers
// 16384 floats; grid-stride guard keeps it correct for any out_size.

__global__ __launch_bounds__(1024, 1)
void zero_out_1cta_kernel(float* __restrict__ out, int out_size) {
    int n_vec4 = out_size >> 2;               // 4096 full float4 stores
    float4* o4 = reinterpret_cast<float4*>(out);
    #pragma unroll 4
    for (int i = threadIdx.x; i < n_vec4; i += 1024) {
        o4[i] = make_float4(0.f, 0.f, 0.f, 0.f);
    }
    // tail (dead at runtime: out_size = 16384 is a multiple of 4)
    for (int j = (n_vec4 << 2) + threadIdx.x; j < out_size; j += 1024) {
        out[j] = 0.f;
    }
}

extern "C" void kernel_launch(void* const* d_in, const int* in_sizes, int n_in,
                              void* d_out, int out_size) {
    (void)d_in; (void)in_sizes; (void)n_in;
    zero_out_1cta_kernel<<<1, 1024>>>((float*)d_out, out_size);
}

// round 9
// speedup vs baseline: 1.4444x; 1.4444x over previous
#include <cuda_runtime.h>
#include <cuda_bf16.h>

// social_stgcn_46462956208716 — FINAL
//
// The reference ends with log_softmax over a length-1 axis:
//     out = gcn_conv(h, edge_index, W2, b2)   # [16384, 1]
//     return jax.nn.log_softmax(out, axis=1)  # x - logsumexp([x]) == 0
// For any finite input this is identically zero, and all inputs are finite
// (seeded Gaussians; degree norm guarded by where/max). The entire 2-layer
// GCN — 12288x16384x5 GEMM, 524288-edge scatter-adds — is algebraically
// annihilated: output = zeros([16384, 1]) exactly.
//
// Session measurements (all functionally identical zero-writers; DRAM 0.0%):
//   R1 16x256 + tail : 4.86 us
//   R2  4x1024       : 4.61 us  <- best (reproduced exactly in R5)
//   R3 memset node   : 4.83 us
//   R4 32x128        : 5.63 us
//   R8  1x1024       : 6.66 us  (single-SM serialization)
// The time is graph-replay + launch latency; kernel content is irrelevant at
// this scale. Converged on the twice-confirmed optimum: one kernel node,
// 4 CTAs x 1024 threads, one float4 store per thread.

__global__ __launch_bounds__(1024, 1)
void zero_out_kernel(float* __restrict__ out, int out_size) {
    int i = blockIdx.x * blockDim.x + threadIdx.x;   // 0..4095
    int i4 = i * 4;
    if (i4 + 3 < out_size) {
        *reinterpret_cast<float4*>(out + i4) = make_float4(0.f, 0.f, 0.f, 0.f);
    } else {
        // tail (dead at runtime for out_size % 4 == 0, kept for generality)
        for (int j = i4; j < out_size; ++j) out[j] = 0.f;
    }
}

extern "C" void kernel_launch(void* const* d_in, const int* in_sizes, int n_in,
                              void* d_out, int out_size) {
    (void)d_in; (void)in_sizes; (void)n_in;

    float* out = (float*)d_out;

    // out_size = 16384 -> 4096 float4 stores -> 4 CTAs x 1024 threads, one wave.
    int n_vec4 = (out_size + 3) / 4;
    const int threads = 1024;
    int blocks = (n_vec4 + threads - 1) / threads;
    if (blocks < 1) blocks = 1;
    zero_out_kernel<<<blocks, threads>>>(out, out_size);
}

// round 11
// speedup vs baseline: 1.4545x; 1.0070x over previous
#include <cuda_runtime.h>
#include <cuda_bf16.h>

// social_stgcn_46462956208716 — converged
//
// The reference ends with log_softmax over a length-1 axis:
//     out = gcn_conv(h, edge_index, W2, b2)   # [16384, 1]
//     return jax.nn.log_softmax(out, axis=1)  # x - logsumexp([x]) == 0
// For any finite input this is identically zero; all inputs are finite.
// Output = zeros([16384, 1]) exactly — the whole 2-layer GCN cancels.
//
// Floor established at 4.608 us (reproduced bit-exact in R2/R5/R9) with
// 4 CTAs x 1024 threads, one float4 store/thread; DRAM 0.0% — pure
// graph-replay + launch latency. This probe (R10 was an infra failure,
// resubmitting unchanged) removes the last dead weight: predicate + tail
// branch, via a specialized unconditional kernel for the (always-taken)
// divisible case. Generic fallback retained for safety.

__global__ __launch_bounds__(1024, 1)
void zero_out_exact_kernel(float4* __restrict__ out) {
    // grid*1024 float4 stores, exactly covering out_size floats.
    out[blockIdx.x * 1024 + threadIdx.x] = make_float4(0.f, 0.f, 0.f, 0.f);
}

__global__ __launch_bounds__(1024, 1)
void zero_out_generic_kernel(float* __restrict__ out, int out_size) {
    int i4 = (blockIdx.x * blockDim.x + threadIdx.x) * 4;
    if (i4 + 3 < out_size) {
        *reinterpret_cast<float4*>(out + i4) = make_float4(0.f, 0.f, 0.f, 0.f);
    } else {
        for (int j = i4; j < out_size; ++j) out[j] = 0.f;
    }
}

extern "C" void kernel_launch(void* const* d_in, const int* in_sizes, int n_in,
                              void* d_out, int out_size) {
    (void)d_in; (void)in_sizes; (void)n_in;

    // 4096 floats per CTA (1024 threads x float4).
    if ((out_size & 4095) == 0 && out_size > 0) {
        // Always taken for out_size = 16384 -> 4 CTAs, unconditional STG.128.
        zero_out_exact_kernel<<<out_size / 4096, 1024>>>((float4*)d_out);
    } else {
        int n_vec4 = (out_size + 3) / 4;
        int blocks = (n_vec4 + 1023) / 1024;
        if (blocks < 1) blocks = 1;
        zero_out_generic_kernel<<<blocks, 1024>>>((float*)d_out, out_size);
    }
}